// round 12
// baseline (speedup 1.0000x reference)
#include <cuda_runtime.h>

// Maxwell RNN: per-row linear recurrence. One warp = one row (8 warps per
// block, R10 config), walked in 32 chunks of 256 elements (8/lane), with a
// DEPTH-2 register prefetch pipeline: chunk c+2's loads are issued as soon
// as chunk c's data is drained, giving loads ~2 chunk-periods of latency
// cover. Zero smem, zero __syncthreads; warps free-run.
//
//   gamma_t = (1 - 0.5*dt)*gamma_{t-1} + 0.5*dt*eps_t,  gamma_{-1} = 0
//   sig_t   = 2.5*eps_t - gamma_{t-1}
// Per chunk, sig is affine in the chunk-start state: sig_j = C_j - Pp_j*g
// (C/Pp overwrite ee/dd in place). Carry: carry = P31*carry + Q31.

constexpr int Bn    = 4096;
constexpr int Tn    = 8192;
constexpr int TPB   = 256;
constexpr int WPB   = TPB / 32;        // 8 warps = 8 rows per block
constexpr int CHUNK = 256;             // elements per warp-chunk
constexpr int EPT   = 8;               // elements per lane per chunk
constexpr int NCH   = Tn / CHUNK;      // 32 chunks per row
constexpr int GRID  = Bn / WPB;        // 512 blocks

__global__ void __launch_bounds__(TPB)
maxwell_warp_kernel(const float* __restrict__ eps, const float* __restrict__ dt,
                    float* __restrict__ out) {
    const int lane = threadIdx.x & 31;
    const int wid  = threadIdx.x >> 5;

    const size_t rb = ((size_t)blockIdx.x * WPB + wid) * Tn;
    const float* pe = eps + rb;
    const float* pd = dt  + rb;
    float*       po = out + rb;
    const int toff = lane * EPT;

    // ---- 2-slot prefetch buffer; fill chunks 0 and 1 ----
    float4 sE[2][2], sD[2][2];
    #pragma unroll
    for (int k = 0; k < 2; k++) {
        const float* qe = pe + k * CHUNK + toff;
        const float* qd = pd + k * CHUNK + toff;
        sE[k][0] = *reinterpret_cast<const float4*>(qe);
        sE[k][1] = *reinterpret_cast<const float4*>(qe + 4);
        sD[k][0] = *reinterpret_cast<const float4*>(qd);
        sD[k][1] = *reinterpret_cast<const float4*>(qd + 4);
    }

    float carry = 0.0f;                 // gamma entering current chunk

    #pragma unroll 2
    for (int c = 0; c < NCH; c++) {
        const int b = c & 1;

        // ---- drain slot b into working registers ----
        float ee[EPT] = { sE[b][0].x, sE[b][0].y, sE[b][0].z, sE[b][0].w,
                          sE[b][1].x, sE[b][1].y, sE[b][1].z, sE[b][1].w };
        float dd[EPT] = { sD[b][0].x, sD[b][0].y, sD[b][0].z, sD[b][0].w,
                          sD[b][1].x, sD[b][1].y, sD[b][1].z, sD[b][1].w };

        // ---- refill slot b with chunk c+2 (prefetch distance 2) ----
        if (c + 2 < NCH) {
            const float* qe = pe + (c + 2) * CHUNK + toff;
            const float* qd = pd + (c + 2) * CHUNK + toff;
            sE[b][0] = *reinterpret_cast<const float4*>(qe);
            sE[b][1] = *reinterpret_cast<const float4*>(qe + 4);
            sD[b][0] = *reinterpret_cast<const float4*>(qd);
            sD[b][1] = *reinterpret_cast<const float4*>(qd + 4);
        }

        // ---- local affine fold; rewrite (ee,dd) -> (C, Pp) in place ----
        float P = 1.0f, Q = 0.0f;
        #pragma unroll
        for (int j = 0; j < EPT; j++) {
            float e = ee[j];
            float d = dd[j];
            dd[j] = P;                      // Pp_j
            ee[j] = fmaf(2.5f, e, -Q);      // C_j
            float ad = 0.5f * d;
            float A  = 1.0f - ad;
            Q = fmaf(A, Q, ad * e);
            P = P * A;
        }

        // ---- warp-inclusive affine scan (5 shuffle steps) ----
        #pragma unroll
        for (int off = 1; off < 32; off <<= 1) {
            float Pu = __shfl_up_sync(0xFFFFFFFFu, P, off);
            float Qu = __shfl_up_sync(0xFFFFFFFFu, Q, off);
            if (lane >= off) { Q = fmaf(P, Qu, Q); P *= Pu; }
        }
        // lane-exclusive prefix -> this lane's chunk-start gamma
        float LPe = __shfl_up_sync(0xFFFFFFFFu, P, 1);
        float LQe = __shfl_up_sync(0xFFFFFFFFu, Q, 1);
        if (lane == 0) { LPe = 1.0f; LQe = 0.0f; }
        float gt = fmaf(LPe, carry, LQe);

        // ---- carry gamma to next chunk (lane-31 inclusive aggregate) ----
        float P31 = __shfl_sync(0xFFFFFFFFu, P, 31);
        float Q31 = __shfl_sync(0xFFFFFFFFu, Q, 31);
        carry = fmaf(P31, carry, Q31);

        // ---- fixup (independent FMAs) + coalesced stores ----
        float4 o0, o1;
        o0.x = fmaf(-dd[0], gt, ee[0]);
        o0.y = fmaf(-dd[1], gt, ee[1]);
        o0.z = fmaf(-dd[2], gt, ee[2]);
        o0.w = fmaf(-dd[3], gt, ee[3]);
        o1.x = fmaf(-dd[4], gt, ee[4]);
        o1.y = fmaf(-dd[5], gt, ee[5]);
        o1.z = fmaf(-dd[6], gt, ee[6]);
        o1.w = fmaf(-dd[7], gt, ee[7]);
        float* w = po + c * CHUNK + toff;
        *reinterpret_cast<float4*>(w)     = o0;
        *reinterpret_cast<float4*>(w + 4) = o1;
    }
}

extern "C" void kernel_launch(void* const* d_in, const int* in_sizes, int n_in,
                              void* d_out, int out_size) {
    const float* eps = (const float*)d_in[0];
    const float* dt  = (const float*)d_in[1];
    float* out = (float*)d_out;

    maxwell_warp_kernel<<<GRID, TPB>>>(eps, dt, out);
}

// round 13
// speedup vs baseline: 1.0902x; 1.0902x over previous
#include <cuda_runtime.h>

// Maxwell RNN: per-row linear recurrence. One warp = one row, 8 warps per
// block, 32 chunks of 256 elements (8/lane), one-chunk register prefetch.
// Zero smem on the hot path, zero __syncthreads; warps free-run.
// R13: 32-bit indexing (33.5M elems < 2^32) + launch_bounds(256,5) to fit
// 5 CTAs/SM -> 40 warps -> ~20KB of loads in flight per SM (MLP was the
// measured shortfall at R10's 25 warps).
//
//   gamma_t = (1 - 0.5*dt)*gamma_{t-1} + 0.5*dt*eps_t,  gamma_{-1} = 0
//   sig_t   = 2.5*eps_t - gamma_{t-1}
// Per chunk, sig is affine in the chunk-start state: sig_j = C_j - Pp_j*g
// (C/Pp overwrite ee/dd in place). Carry: carry = P31*carry + Q31.

constexpr int Bn    = 4096;
constexpr int Tn    = 8192;
constexpr int TPB   = 256;
constexpr int WPB   = TPB / 32;        // 8 warps = 8 rows per block
constexpr int CHUNK = 256;             // elements per warp-chunk
constexpr int EPT   = 8;               // elements per lane per chunk
constexpr int NCH   = Tn / CHUNK;      // 32 chunks per row
constexpr int GRID  = Bn / WPB;        // 512 blocks

__global__ void __launch_bounds__(TPB, 5)
maxwell_warp_kernel(const float* __restrict__ eps, const float* __restrict__ dt,
                    float* __restrict__ out) {
    const int lane = threadIdx.x & 31;
    const int wid  = threadIdx.x >> 5;

    // 32-bit element offset of this lane's first element
    unsigned off = (blockIdx.x * WPB + wid) * (unsigned)Tn + lane * EPT;

    // ---- prefetch chunk 0 ----
    float4 ce0 = *reinterpret_cast<const float4*>(eps + off);
    float4 ce1 = *reinterpret_cast<const float4*>(eps + off + 4);
    float4 cd0 = *reinterpret_cast<const float4*>(dt  + off);
    float4 cd1 = *reinterpret_cast<const float4*>(dt  + off + 4);

    float carry = 0.0f;                 // gamma entering current chunk

    #pragma unroll 2
    for (int c = 0; c < NCH; c++) {
        // ---- prefetch next chunk while current is processed ----
        float4 ne0, ne1, nd0, nd1;
        if (c + 1 < NCH) {
            unsigned noff = off + CHUNK;
            ne0 = *reinterpret_cast<const float4*>(eps + noff);
            ne1 = *reinterpret_cast<const float4*>(eps + noff + 4);
            nd0 = *reinterpret_cast<const float4*>(dt  + noff);
            nd1 = *reinterpret_cast<const float4*>(dt  + noff + 4);
        }

        float ee[EPT] = { ce0.x, ce0.y, ce0.z, ce0.w, ce1.x, ce1.y, ce1.z, ce1.w };
        float dd[EPT] = { cd0.x, cd0.y, cd0.z, cd0.w, cd1.x, cd1.y, cd1.z, cd1.w };

        // ---- local affine fold; rewrite (ee,dd) -> (C, Pp) in place ----
        float P = 1.0f, Q = 0.0f;
        #pragma unroll
        for (int j = 0; j < EPT; j++) {
            float e = ee[j];
            float d = dd[j];
            dd[j] = P;                      // Pp_j
            ee[j] = fmaf(2.5f, e, -Q);      // C_j
            float ad = 0.5f * d;
            float A  = 1.0f - ad;
            Q = fmaf(A, Q, ad * e);
            P = P * A;
        }

        // ---- warp-inclusive affine scan (5 shuffle steps) ----
        #pragma unroll
        for (int s = 1; s < 32; s <<= 1) {
            float Pu = __shfl_up_sync(0xFFFFFFFFu, P, s);
            float Qu = __shfl_up_sync(0xFFFFFFFFu, Q, s);
            if (lane >= s) { Q = fmaf(P, Qu, Q); P *= Pu; }
        }
        // lane-exclusive prefix -> this lane's chunk-start gamma
        float LPe = __shfl_up_sync(0xFFFFFFFFu, P, 1);
        float LQe = __shfl_up_sync(0xFFFFFFFFu, Q, 1);
        if (lane == 0) { LPe = 1.0f; LQe = 0.0f; }
        float gt = fmaf(LPe, carry, LQe);

        // ---- carry gamma to next chunk (lane-31 inclusive aggregate) ----
        float P31 = __shfl_sync(0xFFFFFFFFu, P, 31);
        float Q31 = __shfl_sync(0xFFFFFFFFu, Q, 31);
        carry = fmaf(P31, carry, Q31);

        // ---- fixup (independent FMAs) + coalesced stores ----
        float4 o0, o1;
        o0.x = fmaf(-dd[0], gt, ee[0]);
        o0.y = fmaf(-dd[1], gt, ee[1]);
        o0.z = fmaf(-dd[2], gt, ee[2]);
        o0.w = fmaf(-dd[3], gt, ee[3]);
        o1.x = fmaf(-dd[4], gt, ee[4]);
        o1.y = fmaf(-dd[5], gt, ee[5]);
        o1.z = fmaf(-dd[6], gt, ee[6]);
        o1.w = fmaf(-dd[7], gt, ee[7]);
        *reinterpret_cast<float4*>(out + off)     = o0;
        *reinterpret_cast<float4*>(out + off + 4) = o1;

        ce0 = ne0; ce1 = ne1; cd0 = nd0; cd1 = nd1;
        off += CHUNK;
    }
}

extern "C" void kernel_launch(void* const* d_in, const int* in_sizes, int n_in,
                              void* d_out, int out_size) {
    const float* eps = (const float*)d_in[0];
    const float* dt  = (const float*)d_in[1];
    float* out = (float*)d_out;

    maxwell_warp_kernel<<<GRID, TPB>>>(eps, dt, out);
}